// round 5
// baseline (speedup 1.0000x reference)
#include <cuda_runtime.h>
#include <math.h>
#include <stdint.h>
#include <mma.h>

using namespace nvcuda;

#define B_      16
#define T_      2048
#define F_      512
#define C_      256
#define NEG_    10
#define COPIES  11
#define STEPS_  12
#define U_      16
#define NPART   ((T_ / U_) * B_)

// Scratch (allocation-free rule: __device__ globals)
__device__ float g_tl[(size_t)B_ * T_ * C_];   // 32 MB projected latents
__device__ float g_partials[NPART];

// ---------------------------------------------------------------------------
__device__ __forceinline__ uint32_t smem_u32(const void* p) {
    uint32_t a;
    asm("{ .reg .u64 t; cvta.to.shared.u64 t, %1; cvt.u32.u64 %0, t; }"
        : "=r"(a) : "l"(p));
    return a;
}
__device__ __forceinline__ void cp16(uint32_t dst, const void* src) {
    asm volatile("cp.async.cg.shared.global [%0], [%1], 16;"
                 :: "r"(dst), "l"(src) : "memory");
}
__device__ __forceinline__ void cp_commit() {
    asm volatile("cp.async.commit_group;" ::: "memory");
}
__device__ __forceinline__ void cp_wait1() {
    asm volatile("cp.async.wait_group 1;" ::: "memory");
}
__device__ __forceinline__ void cp_wait0() {
    asm volatile("cp.async.wait_group 0;" ::: "memory");
}

// ---------------------------------------------------------------------------
// Kernel A: tl = true_latent @ Wl + bl via TF32 wmma.
// 128x128 block tile, KC=16, 3-stage cp.async pipeline, 1 sync/iter,
// NO explicit tf32 conversion (HMMA.TF32 reads the tf32 bit-field directly).
// ---------------------------------------------------------------------------
#define GKC     16
#define SB_LD   136                    // 128 + 8 pad
#define SA_SZ   (128 * GKC)            // floats per stage
#define SB_SZ   (GKC * SB_LD)
#define DYN_SM  (3 * (SA_SZ + SB_SZ) * sizeof(float))

__global__ void __launch_bounds__(256, 2) gemm_tl_tc(
    const float* __restrict__ A,     // [B*T, F]
    const float* __restrict__ W,     // [F, C]
    const float* __restrict__ bias)  // [C]
{
    extern __shared__ float dyn[];
    float* sA = dyn;                 // [3][SA_SZ]
    float* sB = dyn + 3 * SA_SZ;     // [3][SB_SZ]
    __shared__ float epi[8][16 * 20];
    __shared__ float bias_s[128];

    const int tid  = threadIdx.x;
    const int bx   = blockIdx.x;   // N tile (0..1)
    const int by   = blockIdx.y;   // M tile (0..255)
    const int wid  = tid >> 5;
    const int lane = tid & 31;
    const int wm   = wid & 3;
    const int wn   = wid >> 2;

    if (tid < 128) bias_s[tid] = bias[bx * 128 + tid];

    wmma::fragment<wmma::accumulator, 16, 16, 8, float> acc[2][4];
#pragma unroll
    for (int i = 0; i < 2; i++)
#pragma unroll
        for (int j = 0; j < 4; j++) wmma::fill_fragment(acc[i][j], 0.f);

    const int idx0 = tid, idx1 = tid + 256;
    const int ar0 = idx0 >> 2, ac0 = (idx0 & 3) << 2;
    const int ar1 = idx1 >> 2, ac1 = (idx1 & 3) << 2;
    const int br0 = idx0 >> 5, bc0 = (idx0 & 31) << 2;
    const int br1 = idx1 >> 5, bc1 = (idx1 & 31) << 2;

    const float* Abase = A + (size_t)(by * 128) * F_;
    const float* Wbase = W + bx * 128;

    const uint32_t sAu = smem_u32(sA);
    const uint32_t sBu = smem_u32(sB);
    const uint32_t dA0 = sAu + (uint32_t)(ar0 * GKC + ac0) * 4u;
    const uint32_t dA1 = sAu + (uint32_t)(ar1 * GKC + ac1) * 4u;
    const uint32_t dB0 = sBu + (uint32_t)(br0 * SB_LD + bc0) * 4u;
    const uint32_t dB1 = sBu + (uint32_t)(br1 * SB_LD + bc1) * 4u;

    auto issue_tile = [&](int k0, int s) {
        uint32_t oA = (uint32_t)s * SA_SZ * 4u;
        uint32_t oB = (uint32_t)s * SB_SZ * 4u;
        cp16(dA0 + oA, Abase + (size_t)ar0 * F_ + k0 + ac0);
        cp16(dA1 + oA, Abase + (size_t)ar1 * F_ + k0 + ac1);
        cp16(dB0 + oB, Wbase + (size_t)(k0 + br0) * C_ + bc0);
        cp16(dB1 + oB, Wbase + (size_t)(k0 + br1) * C_ + bc1);
        cp_commit();
    };

    issue_tile(0, 0);
    issue_tile(GKC, 1);

    const int NIT = F_ / GKC;   // 32
    for (int it = 0; it < NIT; ++it) {
        if (it + 1 < NIT) cp_wait1(); else cp_wait0();
        __syncthreads();
        if (it + 2 < NIT) issue_tile((it + 2) * GKC, (it + 2) % 3);

        const float* cA = sA + (it % 3) * SA_SZ;
        const float* cB = sB + (it % 3) * SB_SZ;
#pragma unroll
        for (int ks = 0; ks < 2; ks++) {
            wmma::fragment<wmma::matrix_a, 16, 16, 8, wmma::precision::tf32, wmma::row_major> af[2];
            wmma::fragment<wmma::matrix_b, 16, 16, 8, wmma::precision::tf32, wmma::row_major> bf[4];
#pragma unroll
            for (int i = 0; i < 2; i++)
                wmma::load_matrix_sync(af[i], cA + (wm * 32 + i * 16) * GKC + ks * 8, GKC);
#pragma unroll
            for (int j = 0; j < 4; j++)
                wmma::load_matrix_sync(bf[j], cB + (ks * 8) * SB_LD + wn * 64 + j * 16, SB_LD);
#pragma unroll
            for (int i = 0; i < 2; i++)
#pragma unroll
                for (int j = 0; j < 4; j++)
                    wmma::mma_sync(acc[i][j], af[i], bf[j], acc[i][j]);
        }
    }
    __syncthreads();

    // Epilogue: per-warp 16x16 smem bounce, add bias, float4 store.
    const int row_l = lane >> 1;
    const int col_l = (lane & 1) * 8;
#pragma unroll
    for (int i = 0; i < 2; i++) {
#pragma unroll
        for (int j = 0; j < 4; j++) {
            wmma::store_matrix_sync(&epi[wid][0], acc[i][j], 20, wmma::mem_row_major);
            __syncwarp();
            int grow = by * 128 + wm * 32 + i * 16 + row_l;
            int bl0  = wn * 64 + j * 16 + col_l;
            int gcol = bx * 128 + bl0;
            float4 o0, o1;
            const float* er = &epi[wid][row_l * 20 + col_l];
            o0.x = er[0] + bias_s[bl0 + 0];
            o0.y = er[1] + bias_s[bl0 + 1];
            o0.z = er[2] + bias_s[bl0 + 2];
            o0.w = er[3] + bias_s[bl0 + 3];
            o1.x = er[4] + bias_s[bl0 + 4];
            o1.y = er[5] + bias_s[bl0 + 5];
            o1.z = er[6] + bias_s[bl0 + 6];
            o1.w = er[7] + bias_s[bl0 + 7];
            *(float4*)&g_tl[(size_t)grow * C_ + gcol]     = o0;
            *(float4*)&g_tl[(size_t)grow * C_ + gcol + 4] = o1;
            __syncwarp();
        }
    }
}

// ---------------------------------------------------------------------------
__device__ __forceinline__ float dot8(float4 a, float4 b, float4 x, float4 y) {
    float s = a.x * x.x;
    s = fmaf(a.y, x.y, s);
    s = fmaf(a.z, x.z, s);
    s = fmaf(a.w, x.w, s);
    s = fmaf(b.x, y.x, s);
    s = fmaf(b.y, y.y, s);
    s = fmaf(b.z, y.z, s);
    s = fmaf(b.w, y.w, s);
    return s;
}

__device__ __forceinline__ void decode_task(int task, int& ul0, int& ul1,
                                            int& c0, int& c1) {
    if (task < 80) {
        int q = task / 5, p = task % 5;
        ul0 = q; ul1 = q; c0 = 2 * p; c1 = 2 * p + 1;
    } else {
        int j = task - 80;
        ul0 = 2 * j; ul1 = 2 * j + 1; c0 = 10; c1 = 10;
    }
}

// ---------------------------------------------------------------------------
// Kernel B: fused dots + logits + logsumexp per (b, u-tile).
// Gathers for task t+1 are issued before task t's FMA+shfl chain.
// ---------------------------------------------------------------------------
__global__ void __launch_bounds__(256) loss_kernel(
    const float* __restrict__ ctx,   // [B, T, C]
    const float* __restrict__ Ws,    // [12]
    const float* __restrict__ bs,    // [12]
    const int*   __restrict__ neg)   // [B, NEG, T]
{
    __shared__ float ctx_s[(U_ + 11) * C_];
    __shared__ float logits_s[U_ * STEPS_ * COPIES];
    __shared__ float ws_s[STEPS_], bs_s[STEPS_];
    __shared__ float red_s[256];

    const int b   = blockIdx.y;
    const int u0  = blockIdx.x * U_;
    const int tid = threadIdx.x;

    if (tid < STEPS_) { ws_s[tid] = Ws[tid]; bs_s[tid] = bs[tid]; }

    const int NROWS = U_ + 11;
    for (int idx = tid; idx < NROWS * (C_ / 4); idx += 256) {
        int j  = idx / (C_ / 4);
        int c4 = (idx % (C_ / 4)) * 4;
        int gr = u0 - 11 + j;
        float4 v4 = make_float4(0.f, 0.f, 0.f, 0.f);
        if (gr >= 0)
            v4 = *(const float4*)(ctx + ((size_t)b * T_ + gr) * C_ + c4);
        *(float4*)&ctx_s[j * C_ + c4] = v4;
    }
    __syncthreads();

    const int warp = tid >> 5, lane = tid & 31;
    const unsigned FULL = 0xffffffffu;

    // Prime task `warp`.
    int task = warp;
    int ul0, ul1, c0, c1;
    decode_task(task, ul0, ul1, c0, c1);
    {
        int ug0 = u0 + ul0, ug1 = u0 + ul1;
        int r0 = (c0 == 0) ? ug0 : neg[((size_t)b * NEG_ + (c0 - 1)) * T_ + ug0];
        int r1 = neg[((size_t)b * NEG_ + (c1 - 1)) * T_ + ug1];
        (void)r0; (void)r1;
    }
    int ug0 = u0 + ul0, ug1 = u0 + ul1;
    int r0 = (c0 == 0) ? ug0 : neg[((size_t)b * NEG_ + (c0 - 1)) * T_ + ug0];
    int r1 = neg[((size_t)b * NEG_ + (c1 - 1)) * T_ + ug1];
    const float4* p0 = (const float4*)(g_tl + ((size_t)b * T_ + r0) * C_);
    const float4* p1 = (const float4*)(g_tl + ((size_t)b * T_ + r1) * C_);
    float4 g0a = p0[lane], g0b = p0[lane + 32];
    float4 g1a = p1[lane], g1b = p1[lane + 32];

    while (task < 88) {
        const int nt = task + 8;
        // Prefetch next task's gathers before this task's compute chain.
        int nul0 = 0, nul1 = 0, nc0 = 0, nc1 = 0;
        float4 n0a, n0b, n1a, n1b;
        if (nt < 88) {
            decode_task(nt, nul0, nul1, nc0, nc1);
            int mg0 = u0 + nul0, mg1 = u0 + nul1;
            int m0 = (nc0 == 0) ? mg0 : neg[((size_t)b * NEG_ + (nc0 - 1)) * T_ + mg0];
            int m1 = neg[((size_t)b * NEG_ + (nc1 - 1)) * T_ + mg1];
            const float4* q0 = (const float4*)(g_tl + ((size_t)b * T_ + m0) * C_);
            const float4* q1 = (const float4*)(g_tl + ((size_t)b * T_ + m1) * C_);
            n0a = q0[lane]; n0b = q0[lane + 32];
            n1a = q1[lane]; n1b = q1[lane + 32];
        }

        float v[32];
        v[12] = (g0a.x + g0a.y) + (g0a.z + g0a.w) + (g0b.x + g0b.y) + (g0b.z + g0b.w);
        v[28] = (g1a.x + g1a.y) + (g1a.z + g1a.w) + (g1b.x + g1b.y) + (g1b.z + g1b.w);
        v[13] = v[14] = v[15] = 0.f;
        v[29] = v[30] = v[31] = 0.f;

        bool same_u = (ul0 == ul1);
#pragma unroll
        for (int i = 0; i < STEPS_; i++) {
            const float4* cr0 = (const float4*)(ctx_s + (ul0 + 11 - i) * C_);
            float4 ca = cr0[lane], cb = cr0[lane + 32];
            v[i] = dot8(ca, cb, g0a, g0b);
            float4 da, db;
            if (same_u) { da = ca; db = cb; }
            else {
                const float4* cr1 = (const float4*)(ctx_s + (ul1 + 11 - i) * C_);
                da = cr1[lane]; db = cr1[lane + 32];
            }
            v[16 + i] = dot8(da, db, g1a, g1b);
        }

        // Folded reduction: 31 shfl; lane l ends with sum over lanes of v[l].
        float t16[16], t8[8], t4[4], t2[2], r;
#pragma unroll
        for (int j = 0; j < 16; j++) {
            float send = (lane & 16) ? v[j] : v[16 + j];
            float keep = (lane & 16) ? v[16 + j] : v[j];
            t16[j] = keep + __shfl_xor_sync(FULL, send, 16);
        }
#pragma unroll
        for (int j = 0; j < 8; j++) {
            float send = (lane & 8) ? t16[j] : t16[8 + j];
            float keep = (lane & 8) ? t16[8 + j] : t16[j];
            t8[j] = keep + __shfl_xor_sync(FULL, send, 8);
        }
#pragma unroll
        for (int j = 0; j < 4; j++) {
            float send = (lane & 4) ? t8[j] : t8[4 + j];
            float keep = (lane & 4) ? t8[4 + j] : t8[j];
            t4[j] = keep + __shfl_xor_sync(FULL, send, 4);
        }
#pragma unroll
        for (int j = 0; j < 2; j++) {
            float send = (lane & 2) ? t4[j] : t4[2 + j];
            float keep = (lane & 2) ? t4[2 + j] : t4[j];
            t2[j] = keep + __shfl_xor_sync(FULL, send, 2);
        }
        {
            float send = (lane & 1) ? t2[0] : t2[1];
            float keep = (lane & 1) ? t2[1] : t2[0];
            r = keep + __shfl_xor_sync(FULL, send, 1);
        }

        float s0t = __shfl_sync(FULL, r, 12);
        float s1t = __shfl_sync(FULL, r, 28);

        if (lane < 12) {
            logits_s[(ul0 * STEPS_ + lane) * COPIES + c0] =
                ws_s[lane] * r + bs_s[lane] * s0t;
        } else if (lane >= 16 && lane < 28) {
            int i = lane - 16;
            logits_s[(ul1 * STEPS_ + i) * COPIES + c1] =
                ws_s[i] * r + bs_s[i] * s1t;
        }

        task = nt;
        ul0 = nul0; ul1 = nul1; c0 = nc0; c1 = nc1;
        g0a = n0a; g0b = n0b; g1a = n1a; g1b = n1b;
    }
    __syncthreads();

    float local = 0.f;
    for (int row = tid; row < U_ * STEPS_; row += 256) {
        int ul = row / STEPS_, i = row % STEPS_;
        int u = u0 + ul;
        if (i <= u) {
            const float* l = &logits_s[row * COPIES];
            float m = l[0];
#pragma unroll
            for (int c = 1; c < COPIES; c++) m = fmaxf(m, l[c]);
            float s = 0.f;
#pragma unroll
            for (int c = 0; c < COPIES; c++) s += expf(l[c] - m);
            local += m + logf(s) - l[0];
        }
    }

    red_s[tid] = local;
    __syncthreads();
    for (int off = 128; off; off >>= 1) {
        if (tid < off) red_s[tid] += red_s[tid + off];
        __syncthreads();
    }
    if (tid == 0)
        g_partials[blockIdx.y * (T_ / U_) + blockIdx.x] = red_s[0];
}

// ---------------------------------------------------------------------------
__global__ void __launch_bounds__(256) final_reduce_kernel(float* __restrict__ out) {
    __shared__ double red[256];
    int tid = threadIdx.x;
    double s = 0.0;
    for (int i = tid; i < NPART; i += 256) s += (double)g_partials[i];
    red[tid] = s;
    __syncthreads();
    for (int off = 128; off; off >>= 1) {
        if (tid < off) red[tid] += red[tid + off];
        __syncthreads();
    }
    if (tid == 0) out[0] = (float)red[0];
}

// ---------------------------------------------------------------------------
extern "C" void kernel_launch(void* const* d_in, const int* in_sizes, int n_in,
                              void* d_out, int out_size) {
    const float* true_latent = (const float*)d_in[0];   // [B,T,F]
    const float* ctx         = (const float*)d_in[1];   // [B,T,C]
    const float* Wl          = (const float*)d_in[2];   // [F,C]
    const float* bl          = (const float*)d_in[3];   // [C]
    const float* Ws          = (const float*)d_in[4];   // [12]
    const float* bs          = (const float*)d_in[5];   // [12]
    const int*   neg         = (const int*)d_in[6];     // [B,NEG,T]
    float* out = (float*)d_out;

    cudaFuncSetAttribute(gemm_tl_tc, cudaFuncAttributeMaxDynamicSharedMemorySize,
                         (int)DYN_SM);

    gemm_tl_tc<<<dim3(C_ / 128, (B_ * T_) / 128), 256, DYN_SM>>>(true_latent, Wl, bl);
    loss_kernel<<<dim3(T_ / U_, B_), 256>>>(ctx, Ws, bs, neg);
    final_reduce_kernel<<<1, 256>>>(out);
}

// round 6
// speedup vs baseline: 1.0826x; 1.0826x over previous
#include <cuda_runtime.h>
#include <math.h>
#include <stdint.h>
#include <mma.h>

using namespace nvcuda;

#define B_      16
#define T_      2048
#define F_      512
#define C_      256
#define NEG_    10
#define COPIES  11
#define STEPS_  12
#define U_      16
#define NPART   ((T_ / U_) * B_)

// Scratch (allocation-free rule: __device__ globals)
__device__ float g_tl[(size_t)B_ * T_ * C_];   // 32 MB projected latents
__device__ float g_partials[NPART];

// ---------------------------------------------------------------------------
__device__ __forceinline__ uint32_t smem_u32(const void* p) {
    uint32_t a;
    asm("{ .reg .u64 t; cvta.to.shared.u64 t, %1; cvt.u32.u64 %0, t; }"
        : "=r"(a) : "l"(p));
    return a;
}
__device__ __forceinline__ void cp16(uint32_t dst, const void* src) {
    asm volatile("cp.async.cg.shared.global [%0], [%1], 16;"
                 :: "r"(dst), "l"(src) : "memory");
}
__device__ __forceinline__ void cp_commit() {
    asm volatile("cp.async.commit_group;" ::: "memory");
}
__device__ __forceinline__ void cp_wait1() {
    asm volatile("cp.async.wait_group 1;" ::: "memory");
}
__device__ __forceinline__ void cp_wait0() {
    asm volatile("cp.async.wait_group 0;" ::: "memory");
}

// ---------------------------------------------------------------------------
// Kernel A: tl = true_latent @ Wl + bl via TF32 wmma (RN conversions kept).
// 128x128 block tile, KC=32, 2-stage cp.async pipeline, 1 sync/iter (16 iters).
// A smem ld padded to 36 floats (4-bank row shift) to cut LDS conflicts.
// ---------------------------------------------------------------------------
#define GKC     32
#define SA_LD   36
#define SB_LD   136
#define SA_SZ   (128 * SA_LD)
#define SB_SZ   (GKC * SB_LD)
#define DYN_SM  (2 * (SA_SZ + SB_SZ) * sizeof(float))

__global__ void __launch_bounds__(256, 2) gemm_tl_tc(
    const float* __restrict__ A,     // [B*T, F]
    const float* __restrict__ W,     // [F, C]
    const float* __restrict__ bias)  // [C]
{
    extern __shared__ float dyn[];
    float* sA = dyn;                 // [2][SA_SZ]
    float* sB = dyn + 2 * SA_SZ;     // [2][SB_SZ]
    __shared__ float epi[8][16 * 20];
    __shared__ float bias_s[128];

    const int tid  = threadIdx.x;
    const int bx   = blockIdx.x;   // N tile (0..1)
    const int by   = blockIdx.y;   // M tile (0..255)
    const int wid  = tid >> 5;
    const int lane = tid & 31;
    const int wm   = wid & 3;
    const int wn   = wid >> 2;

    if (tid < 128) bias_s[tid] = bias[bx * 128 + tid];

    wmma::fragment<wmma::accumulator, 16, 16, 8, float> acc[2][4];
#pragma unroll
    for (int i = 0; i < 2; i++)
#pragma unroll
        for (int j = 0; j < 4; j++) wmma::fill_fragment(acc[i][j], 0.f);

    // A tile: 128 rows x 32 k = 1024 16B-chunks; B tile: 32 rows x 128 cols.
    const float* Abase = A + (size_t)(by * 128) * F_;
    const float* Wbase = W + bx * 128;

    const uint32_t sAu = smem_u32(sA);
    const uint32_t sBu = smem_u32(sB);

    uint32_t dA[4], dB[4];
    int arow[4], acol[4], brow[4], bcol[4];
#pragma unroll
    for (int q = 0; q < 4; q++) {
        int idx = tid + q * 256;
        arow[q] = idx >> 3;  acol[q] = (idx & 7) << 2;
        brow[q] = idx >> 5;  bcol[q] = (idx & 31) << 2;
        dA[q] = sAu + (uint32_t)(arow[q] * SA_LD + acol[q]) * 4u;
        dB[q] = sBu + (uint32_t)(brow[q] * SB_LD + bcol[q]) * 4u;
    }

    auto issue_tile = [&](int k0, int s) {
        uint32_t oA = (uint32_t)s * SA_SZ * 4u;
        uint32_t oB = (uint32_t)s * SB_SZ * 4u;
#pragma unroll
        for (int q = 0; q < 4; q++)
            cp16(dA[q] + oA, Abase + (size_t)arow[q] * F_ + k0 + acol[q]);
#pragma unroll
        for (int q = 0; q < 4; q++)
            cp16(dB[q] + oB, Wbase + (size_t)(k0 + brow[q]) * C_ + bcol[q]);
        cp_commit();
    };

    issue_tile(0, 0);

    const int NIT = F_ / GKC;   // 16
    for (int it = 0; it < NIT; ++it) {
        if (it + 1 < NIT) {
            issue_tile((it + 1) * GKC, (it + 1) & 1);
            cp_wait1();
        } else {
            cp_wait0();
        }
        __syncthreads();

        const float* cA = sA + (it & 1) * SA_SZ;
        const float* cB = sB + (it & 1) * SB_SZ;
#pragma unroll
        for (int ks = 0; ks < 4; ks++) {
            wmma::fragment<wmma::matrix_a, 16, 16, 8, wmma::precision::tf32, wmma::row_major> af[2];
            wmma::fragment<wmma::matrix_b, 16, 16, 8, wmma::precision::tf32, wmma::row_major> bf[4];
#pragma unroll
            for (int i = 0; i < 2; i++) {
                wmma::load_matrix_sync(af[i], cA + (wm * 32 + i * 16) * SA_LD + ks * 8, SA_LD);
#pragma unroll
                for (int e = 0; e < af[i].num_elements; e++)
                    af[i].x[e] = wmma::__float_to_tf32(af[i].x[e]);
            }
#pragma unroll
            for (int j = 0; j < 4; j++) {
                wmma::load_matrix_sync(bf[j], cB + (ks * 8) * SB_LD + wn * 64 + j * 16, SB_LD);
#pragma unroll
                for (int e = 0; e < bf[j].num_elements; e++)
                    bf[j].x[e] = wmma::__float_to_tf32(bf[j].x[e]);
            }
#pragma unroll
            for (int i = 0; i < 2; i++)
#pragma unroll
                for (int j = 0; j < 4; j++)
                    wmma::mma_sync(acc[i][j], af[i], bf[j], acc[i][j]);
        }
        __syncthreads();
    }

    // Epilogue: per-warp 16x16 smem bounce, add bias, float4 store.
    const int row_l = lane >> 1;
    const int col_l = (lane & 1) * 8;
#pragma unroll
    for (int i = 0; i < 2; i++) {
#pragma unroll
        for (int j = 0; j < 4; j++) {
            wmma::store_matrix_sync(&epi[wid][0], acc[i][j], 20, wmma::mem_row_major);
            __syncwarp();
            int grow = by * 128 + wm * 32 + i * 16 + row_l;
            int bl0  = wn * 64 + j * 16 + col_l;
            int gcol = bx * 128 + bl0;
            float4 o0, o1;
            const float* er = &epi[wid][row_l * 20 + col_l];
            o0.x = er[0] + bias_s[bl0 + 0];
            o0.y = er[1] + bias_s[bl0 + 1];
            o0.z = er[2] + bias_s[bl0 + 2];
            o0.w = er[3] + bias_s[bl0 + 3];
            o1.x = er[4] + bias_s[bl0 + 4];
            o1.y = er[5] + bias_s[bl0 + 5];
            o1.z = er[6] + bias_s[bl0 + 6];
            o1.w = er[7] + bias_s[bl0 + 7];
            *(float4*)&g_tl[(size_t)grow * C_ + gcol]     = o0;
            *(float4*)&g_tl[(size_t)grow * C_ + gcol + 4] = o1;
            __syncwarp();
        }
    }
}

// ---------------------------------------------------------------------------
__device__ __forceinline__ float dot8(float4 a, float4 b, float4 x, float4 y) {
    float s = a.x * x.x;
    s = fmaf(a.y, x.y, s);
    s = fmaf(a.z, x.z, s);
    s = fmaf(a.w, x.w, s);
    s = fmaf(b.x, y.x, s);
    s = fmaf(b.y, y.y, s);
    s = fmaf(b.z, y.z, s);
    s = fmaf(b.w, y.w, s);
    return s;
}

// ---------------------------------------------------------------------------
// Kernel B: fused dots + logits + logsumexp per (b, u-tile). (R4 structure)
// ---------------------------------------------------------------------------
__global__ void __launch_bounds__(256) loss_kernel(
    const float* __restrict__ ctx,   // [B, T, C]
    const float* __restrict__ Ws,    // [12]
    const float* __restrict__ bs,    // [12]
    const int*   __restrict__ neg)   // [B, NEG, T]
{
    __shared__ float ctx_s[(U_ + 11) * C_];
    __shared__ float logits_s[U_ * STEPS_ * COPIES];
    __shared__ float ws_s[STEPS_], bs_s[STEPS_];
    __shared__ float red_s[256];

    const int b   = blockIdx.y;
    const int u0  = blockIdx.x * U_;
    const int tid = threadIdx.x;

    if (tid < STEPS_) { ws_s[tid] = Ws[tid]; bs_s[tid] = bs[tid]; }

    const int NROWS = U_ + 11;
    for (int idx = tid; idx < NROWS * (C_ / 4); idx += 256) {
        int j  = idx / (C_ / 4);
        int c4 = (idx % (C_ / 4)) * 4;
        int gr = u0 - 11 + j;
        float4 v4 = make_float4(0.f, 0.f, 0.f, 0.f);
        if (gr >= 0)
            v4 = *(const float4*)(ctx + ((size_t)b * T_ + gr) * C_ + c4);
        *(float4*)&ctx_s[j * C_ + c4] = v4;
    }
    __syncthreads();

    const int warp = tid >> 5, lane = tid & 31;
    const unsigned FULL = 0xffffffffu;

    for (int task = warp; task < 88; task += 8) {
        int ul0, ul1, c0, c1;
        if (task < 80) {
            int q = task / 5, p = task % 5;
            ul0 = q; ul1 = q; c0 = 2 * p; c1 = 2 * p + 1;
        } else {
            int j = task - 80;
            ul0 = 2 * j; ul1 = 2 * j + 1; c0 = 10; c1 = 10;
        }
        int ug0 = u0 + ul0, ug1 = u0 + ul1;
        int r0 = (c0 == 0) ? ug0 : neg[((size_t)b * NEG_ + (c0 - 1)) * T_ + ug0];
        int r1 = neg[((size_t)b * NEG_ + (c1 - 1)) * T_ + ug1];

        const float4* p0 = (const float4*)(g_tl + ((size_t)b * T_ + r0) * C_);
        const float4* p1 = (const float4*)(g_tl + ((size_t)b * T_ + r1) * C_);
        float4 g0a = p0[lane], g0b = p0[lane + 32];
        float4 g1a = p1[lane], g1b = p1[lane + 32];

        float v[32];
        v[12] = (g0a.x + g0a.y) + (g0a.z + g0a.w) + (g0b.x + g0b.y) + (g0b.z + g0b.w);
        v[28] = (g1a.x + g1a.y) + (g1a.z + g1a.w) + (g1b.x + g1b.y) + (g1b.z + g1b.w);
        v[13] = v[14] = v[15] = 0.f;
        v[29] = v[30] = v[31] = 0.f;

        bool same_u = (ul0 == ul1);
#pragma unroll
        for (int i = 0; i < STEPS_; i++) {
            const float4* cr0 = (const float4*)(ctx_s + (ul0 + 11 - i) * C_);
            float4 ca = cr0[lane], cb = cr0[lane + 32];
            v[i] = dot8(ca, cb, g0a, g0b);
            float4 da, db;
            if (same_u) { da = ca; db = cb; }
            else {
                const float4* cr1 = (const float4*)(ctx_s + (ul1 + 11 - i) * C_);
                da = cr1[lane]; db = cr1[lane + 32];
            }
            v[16 + i] = dot8(da, db, g1a, g1b);
        }

        // Folded reduction: 31 shfl; lane l ends with sum over lanes of v[l].
        float t16[16], t8[8], t4[4], t2[2], r;
#pragma unroll
        for (int j = 0; j < 16; j++) {
            float send = (lane & 16) ? v[j] : v[16 + j];
            float keep = (lane & 16) ? v[16 + j] : v[j];
            t16[j] = keep + __shfl_xor_sync(FULL, send, 16);
        }
#pragma unroll
        for (int j = 0; j < 8; j++) {
            float send = (lane & 8) ? t16[j] : t16[8 + j];
            float keep = (lane & 8) ? t16[8 + j] : t16[j];
            t8[j] = keep + __shfl_xor_sync(FULL, send, 8);
        }
#pragma unroll
        for (int j = 0; j < 4; j++) {
            float send = (lane & 4) ? t8[j] : t8[4 + j];
            float keep = (lane & 4) ? t8[4 + j] : t8[j];
            t4[j] = keep + __shfl_xor_sync(FULL, send, 4);
        }
#pragma unroll
        for (int j = 0; j < 2; j++) {
            float send = (lane & 2) ? t4[j] : t4[2 + j];
            float keep = (lane & 2) ? t4[2 + j] : t4[j];
            t2[j] = keep + __shfl_xor_sync(FULL, send, 2);
        }
        {
            float send = (lane & 1) ? t2[0] : t2[1];
            float keep = (lane & 1) ? t2[1] : t2[0];
            r = keep + __shfl_xor_sync(FULL, send, 1);
        }

        float s0t = __shfl_sync(FULL, r, 12);
        float s1t = __shfl_sync(FULL, r, 28);

        if (lane < 12) {
            logits_s[(ul0 * STEPS_ + lane) * COPIES + c0] =
                ws_s[lane] * r + bs_s[lane] * s0t;
        } else if (lane >= 16 && lane < 28) {
            int i = lane - 16;
            logits_s[(ul1 * STEPS_ + i) * COPIES + c1] =
                ws_s[i] * r + bs_s[i] * s1t;
        }
    }
    __syncthreads();

    float local = 0.f;
    for (int row = tid; row < U_ * STEPS_; row += 256) {
        int ul = row / STEPS_, i = row % STEPS_;
        int u = u0 + ul;
        if (i <= u) {
            const float* l = &logits_s[row * COPIES];
            float m = l[0];
#pragma unroll
            for (int c = 1; c < COPIES; c++) m = fmaxf(m, l[c]);
            float s = 0.f;
#pragma unroll
            for (int c = 0; c < COPIES; c++) s += expf(l[c] - m);
            local += m + logf(s) - l[0];
        }
    }

    red_s[tid] = local;
    __syncthreads();
    for (int off = 128; off; off >>= 1) {
        if (tid < off) red_s[tid] += red_s[tid + off];
        __syncthreads();
    }
    if (tid == 0)
        g_partials[blockIdx.y * (T_ / U_) + blockIdx.x] = red_s[0];
}

// ---------------------------------------------------------------------------
__global__ void __launch_bounds__(256) final_reduce_kernel(float* __restrict__ out) {
    __shared__ double red[256];
    int tid = threadIdx.x;
    double s = 0.0;
    for (int i = tid; i < NPART; i += 256) s += (double)g_partials[i];
    red[tid] = s;
    __syncthreads();
    for (int off = 128; off; off >>= 1) {
        if (tid < off) red[tid] += red[tid + off];
        __syncthreads();
    }
    if (tid == 0) out[0] = (float)red[0];
}

// ---------------------------------------------------------------------------
extern "C" void kernel_launch(void* const* d_in, const int* in_sizes, int n_in,
                              void* d_out, int out_size) {
    const float* true_latent = (const float*)d_in[0];   // [B,T,F]
    const float* ctx         = (const float*)d_in[1];   // [B,T,C]
    const float* Wl          = (const float*)d_in[2];   // [F,C]
    const float* bl          = (const float*)d_in[3];   // [C]
    const float* Ws          = (const float*)d_in[4];   // [12]
    const float* bs          = (const float*)d_in[5];   // [12]
    const int*   neg         = (const int*)d_in[6];     // [B,NEG,T]
    float* out = (float*)d_out;

    cudaFuncSetAttribute(gemm_tl_tc, cudaFuncAttributeMaxDynamicSharedMemorySize,
                         (int)DYN_SM);

    gemm_tl_tc<<<dim3(C_ / 128, (B_ * T_) / 128), 256, DYN_SM>>>(true_latent, Wl, bl);
    loss_kernel<<<dim3(T_ / U_, B_), 256>>>(ctx, Ws, bs, neg);
    final_reduce_kernel<<<1, 256>>>(out);
}

// round 7
// speedup vs baseline: 1.3806x; 1.2752x over previous
#include <cuda_runtime.h>
#include <cuda_bf16.h>
#include <math.h>
#include <stdint.h>
#include <mma.h>

using namespace nvcuda;

#define B_      16
#define T_      2048
#define F_      512
#define C_      256
#define NEG_    10
#define COPIES  11
#define STEPS_  12
#define U_      16
#define NPART   ((T_ / U_) * B_)

#define NA_ ((size_t)B_ * T_ * F_)     // 16,777,216
#define NW_ ((size_t)F_ * C_)          // 131,072

// Scratch (allocation-free rule: __device__ globals)
__device__ float          g_tl[(size_t)B_ * T_ * C_];   // 32 MB projected latents
__device__ __nv_bfloat16  g_A16[NA_];                   // 32 MB bf16 inputs
__device__ __nv_bfloat16  g_W16[NW_];
__device__ float          g_partials[NPART];

// ---------------------------------------------------------------------------
__device__ __forceinline__ uint32_t smem_u32(const void* p) {
    uint32_t a;
    asm("{ .reg .u64 t; cvta.to.shared.u64 t, %1; cvt.u32.u64 %0, t; }"
        : "=r"(a) : "l"(p));
    return a;
}
__device__ __forceinline__ void cp16(uint32_t dst, const void* src) {
    asm volatile("cp.async.cg.shared.global [%0], [%1], 16;"
                 :: "r"(dst), "l"(src) : "memory");
}
__device__ __forceinline__ void cp_commit() {
    asm volatile("cp.async.commit_group;" ::: "memory");
}
__device__ __forceinline__ void cp_wait1() {
    asm volatile("cp.async.wait_group 1;" ::: "memory");
}
__device__ __forceinline__ void cp_wait0() {
    asm volatile("cp.async.wait_group 0;" ::: "memory");
}

// ---------------------------------------------------------------------------
// Kernel 0: fp32 -> bf16 (RN) for A and W.
// ---------------------------------------------------------------------------
__global__ void __launch_bounds__(256) convert_bf16(
    const float* __restrict__ A, const float* __restrict__ W)
{
    const size_t nA4 = NA_ / 4, nW4 = NW_ / 4;
    const size_t stride = (size_t)gridDim.x * blockDim.x;
    for (size_t i = (size_t)blockIdx.x * blockDim.x + threadIdx.x;
         i < nA4 + nW4; i += stride) {
        union { __nv_bfloat162 h2[2]; uint2 u; } pk;
        if (i < nA4) {
            float4 v = ((const float4*)A)[i];
            pk.h2[0] = __float22bfloat162_rn(make_float2(v.x, v.y));
            pk.h2[1] = __float22bfloat162_rn(make_float2(v.z, v.w));
            ((uint2*)g_A16)[i] = pk.u;
        } else {
            size_t j = i - nA4;
            float4 v = ((const float4*)W)[j];
            pk.h2[0] = __float22bfloat162_rn(make_float2(v.x, v.y));
            pk.h2[1] = __float22bfloat162_rn(make_float2(v.z, v.w));
            ((uint2*)g_W16)[j] = pk.u;
        }
    }
}

// ---------------------------------------------------------------------------
// Kernel A: tl = A16 @ W16 + bl via BF16 wmma (16x16x16), fp32 accumulate.
// 128x128 block tile, KC=32, 2-stage cp.async pipeline.
// ---------------------------------------------------------------------------
#define GKC     32
#define SA_LD   40                      // bf16 elems (32 + 8 pad)
#define SB_LD   136                     // 128 + 8 pad
#define SA_SZ   (128 * SA_LD)           // bf16 elems per stage
#define SB_SZ   (GKC * SB_LD)
#define DYN_SM  (2 * (SA_SZ + SB_SZ) * sizeof(__nv_bfloat16))

__global__ void __launch_bounds__(256, 2) gemm_tl_tc(
    const float* __restrict__ bias)  // [C]
{
    extern __shared__ __nv_bfloat16 dynb[];
    __nv_bfloat16* sA = dynb;                 // [2][SA_SZ]
    __nv_bfloat16* sB = dynb + 2 * SA_SZ;     // [2][SB_SZ]
    __shared__ float epi[8][16 * 20];
    __shared__ float bias_s[128];

    const int tid  = threadIdx.x;
    const int bx   = blockIdx.x;   // N tile (0..1)
    const int by   = blockIdx.y;   // M tile (0..255)
    const int wid  = tid >> 5;
    const int lane = tid & 31;
    const int wm   = wid & 3;
    const int wn   = wid >> 2;

    if (tid < 128) bias_s[tid] = bias[bx * 128 + tid];

    wmma::fragment<wmma::accumulator, 16, 16, 16, float> acc[2][4];
#pragma unroll
    for (int i = 0; i < 2; i++)
#pragma unroll
        for (int j = 0; j < 4; j++) wmma::fill_fragment(acc[i][j], 0.f);

    const __nv_bfloat16* Abase = g_A16 + (size_t)(by * 128) * F_;
    const __nv_bfloat16* Wbase = g_W16 + bx * 128;

    const uint32_t sAu = smem_u32(sA);
    const uint32_t sBu = smem_u32(sB);

    // A tile: 128 rows x 32 bf16 = 512 16B chunks; B tile: 32 x 128 = 512.
    uint32_t dA[2], dB[2];
    int arow[2], acol[2], brow[2], bcol[2];
#pragma unroll
    for (int q = 0; q < 2; q++) {
        int idx = tid + q * 256;
        arow[q] = idx >> 2;  acol[q] = (idx & 3) << 3;    // elements
        brow[q] = idx >> 4;  bcol[q] = (idx & 15) << 3;
        dA[q] = sAu + (uint32_t)(arow[q] * SA_LD + acol[q]) * 2u;
        dB[q] = sBu + (uint32_t)(brow[q] * SB_LD + bcol[q]) * 2u;
    }

    auto issue_tile = [&](int k0, int s) {
        uint32_t oA = (uint32_t)s * SA_SZ * 2u;
        uint32_t oB = (uint32_t)s * SB_SZ * 2u;
#pragma unroll
        for (int q = 0; q < 2; q++)
            cp16(dA[q] + oA, Abase + (size_t)arow[q] * F_ + k0 + acol[q]);
#pragma unroll
        for (int q = 0; q < 2; q++)
            cp16(dB[q] + oB, Wbase + (size_t)(k0 + brow[q]) * C_ + bcol[q]);
        cp_commit();
    };

    issue_tile(0, 0);

    const int NIT = F_ / GKC;   // 16
    for (int it = 0; it < NIT; ++it) {
        if (it + 1 < NIT) {
            issue_tile((it + 1) * GKC, (it + 1) & 1);
            cp_wait1();
        } else {
            cp_wait0();
        }
        __syncthreads();

        const __nv_bfloat16* cA = sA + (it & 1) * SA_SZ;
        const __nv_bfloat16* cB = sB + (it & 1) * SB_SZ;
#pragma unroll
        for (int ks = 0; ks < 2; ks++) {
            wmma::fragment<wmma::matrix_a, 16, 16, 16, __nv_bfloat16, wmma::row_major> af[2];
            wmma::fragment<wmma::matrix_b, 16, 16, 16, __nv_bfloat16, wmma::row_major> bf[4];
#pragma unroll
            for (int i = 0; i < 2; i++)
                wmma::load_matrix_sync(af[i], cA + (wm * 32 + i * 16) * SA_LD + ks * 16, SA_LD);
#pragma unroll
            for (int j = 0; j < 4; j++)
                wmma::load_matrix_sync(bf[j], cB + (ks * 16) * SB_LD + wn * 64 + j * 16, SB_LD);
#pragma unroll
            for (int i = 0; i < 2; i++)
#pragma unroll
                for (int j = 0; j < 4; j++)
                    wmma::mma_sync(acc[i][j], af[i], bf[j], acc[i][j]);
        }
        __syncthreads();
    }

    // Epilogue: per-warp 16x16 smem bounce, add bias, float4 store.
    const int row_l = lane >> 1;
    const int col_l = (lane & 1) * 8;
#pragma unroll
    for (int i = 0; i < 2; i++) {
#pragma unroll
        for (int j = 0; j < 4; j++) {
            wmma::store_matrix_sync(&epi[wid][0], acc[i][j], 20, wmma::mem_row_major);
            __syncwarp();
            int grow = by * 128 + wm * 32 + i * 16 + row_l;
            int bl0  = wn * 64 + j * 16 + col_l;
            int gcol = bx * 128 + bl0;
            float4 o0, o1;
            const float* er = &epi[wid][row_l * 20 + col_l];
            o0.x = er[0] + bias_s[bl0 + 0];
            o0.y = er[1] + bias_s[bl0 + 1];
            o0.z = er[2] + bias_s[bl0 + 2];
            o0.w = er[3] + bias_s[bl0 + 3];
            o1.x = er[4] + bias_s[bl0 + 4];
            o1.y = er[5] + bias_s[bl0 + 5];
            o1.z = er[6] + bias_s[bl0 + 6];
            o1.w = er[7] + bias_s[bl0 + 7];
            *(float4*)&g_tl[(size_t)grow * C_ + gcol]     = o0;
            *(float4*)&g_tl[(size_t)grow * C_ + gcol + 4] = o1;
            __syncwarp();
        }
    }
}

// ---------------------------------------------------------------------------
__device__ __forceinline__ float dot8(float4 a, float4 b, float4 x, float4 y) {
    float s = a.x * x.x;
    s = fmaf(a.y, x.y, s);
    s = fmaf(a.z, x.z, s);
    s = fmaf(a.w, x.w, s);
    s = fmaf(b.x, y.x, s);
    s = fmaf(b.y, y.y, s);
    s = fmaf(b.z, y.z, s);
    s = fmaf(b.w, y.w, s);
    return s;
}

// ---------------------------------------------------------------------------
// Kernel B: fused dots + logits + logsumexp per (b, u-tile). (unchanged)
// ---------------------------------------------------------------------------
__global__ void __launch_bounds__(256) loss_kernel(
    const float* __restrict__ ctx,   // [B, T, C]
    const float* __restrict__ Ws,    // [12]
    const float* __restrict__ bs,    // [12]
    const int*   __restrict__ neg)   // [B, NEG, T]
{
    __shared__ float ctx_s[(U_ + 11) * C_];
    __shared__ float logits_s[U_ * STEPS_ * COPIES];
    __shared__ float ws_s[STEPS_], bs_s[STEPS_];
    __shared__ float red_s[256];

    const int b   = blockIdx.y;
    const int u0  = blockIdx.x * U_;
    const int tid = threadIdx.x;

    if (tid < STEPS_) { ws_s[tid] = Ws[tid]; bs_s[tid] = bs[tid]; }

    const int NROWS = U_ + 11;
    for (int idx = tid; idx < NROWS * (C_ / 4); idx += 256) {
        int j  = idx / (C_ / 4);
        int c4 = (idx % (C_ / 4)) * 4;
        int gr = u0 - 11 + j;
        float4 v4 = make_float4(0.f, 0.f, 0.f, 0.f);
        if (gr >= 0)
            v4 = *(const float4*)(ctx + ((size_t)b * T_ + gr) * C_ + c4);
        *(float4*)&ctx_s[j * C_ + c4] = v4;
    }
    __syncthreads();

    const int warp = tid >> 5, lane = tid & 31;
    const unsigned FULL = 0xffffffffu;

    for (int task = warp; task < 88; task += 8) {
        int ul0, ul1, c0, c1;
        if (task < 80) {
            int q = task / 5, p = task % 5;
            ul0 = q; ul1 = q; c0 = 2 * p; c1 = 2 * p + 1;
        } else {
            int j = task - 80;
            ul0 = 2 * j; ul1 = 2 * j + 1; c0 = 10; c1 = 10;
        }
        int ug0 = u0 + ul0, ug1 = u0 + ul1;
        int r0 = (c0 == 0) ? ug0 : neg[((size_t)b * NEG_ + (c0 - 1)) * T_ + ug0];
        int r1 = neg[((size_t)b * NEG_ + (c1 - 1)) * T_ + ug1];

        const float4* p0 = (const float4*)(g_tl + ((size_t)b * T_ + r0) * C_);
        const float4* p1 = (const float4*)(g_tl + ((size_t)b * T_ + r1) * C_);
        float4 g0a = p0[lane], g0b = p0[lane + 32];
        float4 g1a = p1[lane], g1b = p1[lane + 32];

        float v[32];
        v[12] = (g0a.x + g0a.y) + (g0a.z + g0a.w) + (g0b.x + g0b.y) + (g0b.z + g0b.w);
        v[28] = (g1a.x + g1a.y) + (g1a.z + g1a.w) + (g1b.x + g1b.y) + (g1b.z + g1b.w);
        v[13] = v[14] = v[15] = 0.f;
        v[29] = v[30] = v[31] = 0.f;

        bool same_u = (ul0 == ul1);
#pragma unroll
        for (int i = 0; i < STEPS_; i++) {
            const float4* cr0 = (const float4*)(ctx_s + (ul0 + 11 - i) * C_);
            float4 ca = cr0[lane], cb = cr0[lane + 32];
            v[i] = dot8(ca, cb, g0a, g0b);
            float4 da, db;
            if (same_u) { da = ca; db = cb; }
            else {
                const float4* cr1 = (const float4*)(ctx_s + (ul1 + 11 - i) * C_);
                da = cr1[lane]; db = cr1[lane + 32];
            }
            v[16 + i] = dot8(da, db, g1a, g1b);
        }

        // Folded reduction: 31 shfl; lane l ends with sum over lanes of v[l].
        float t16[16], t8[8], t4[4], t2[2], r;
#pragma unroll
        for (int j = 0; j < 16; j++) {
            float send = (lane & 16) ? v[j] : v[16 + j];
            float keep = (lane & 16) ? v[16 + j] : v[j];
            t16[j] = keep + __shfl_xor_sync(FULL, send, 16);
        }
#pragma unroll
        for (int j = 0; j < 8; j++) {
            float send = (lane & 8) ? t16[j] : t16[8 + j];
            float keep = (lane & 8) ? t16[8 + j] : t16[j];
            t8[j] = keep + __shfl_xor_sync(FULL, send, 8);
        }
#pragma unroll
        for (int j = 0; j < 4; j++) {
            float send = (lane & 4) ? t8[j] : t8[4 + j];
            float keep = (lane & 4) ? t8[4 + j] : t8[j];
            t4[j] = keep + __shfl_xor_sync(FULL, send, 4);
        }
#pragma unroll
        for (int j = 0; j < 2; j++) {
            float send = (lane & 2) ? t4[j] : t4[2 + j];
            float keep = (lane & 2) ? t4[2 + j] : t4[j];
            t2[j] = keep + __shfl_xor_sync(FULL, send, 2);
        }
        {
            float send = (lane & 1) ? t2[0] : t2[1];
            float keep = (lane & 1) ? t2[1] : t2[0];
            r = keep + __shfl_xor_sync(FULL, send, 1);
        }

        float s0t = __shfl_sync(FULL, r, 12);
        float s1t = __shfl_sync(FULL, r, 28);

        if (lane < 12) {
            logits_s[(ul0 * STEPS_ + lane) * COPIES + c0] =
                ws_s[lane] * r + bs_s[lane] * s0t;
        } else if (lane >= 16 && lane < 28) {
            int i = lane - 16;
            logits_s[(ul1 * STEPS_ + i) * COPIES + c1] =
                ws_s[i] * r + bs_s[i] * s1t;
        }
    }
    __syncthreads();

    float local = 0.f;
    for (int row = tid; row < U_ * STEPS_; row += 256) {
        int ul = row / STEPS_, i = row % STEPS_;
        int u = u0 + ul;
        if (i <= u) {
            const float* l = &logits_s[row * COPIES];
            float m = l[0];
#pragma unroll
            for (int c = 1; c < COPIES; c++) m = fmaxf(m, l[c]);
            float s = 0.f;
#pragma unroll
            for (int c = 0; c < COPIES; c++) s += expf(l[c] - m);
            local += m + logf(s) - l[0];
        }
    }

    red_s[tid] = local;
    __syncthreads();
    for (int off = 128; off; off >>= 1) {
        if (tid < off) red_s[tid] += red_s[tid + off];
        __syncthreads();
    }
    if (tid == 0)
        g_partials[blockIdx.y * (T_ / U_) + blockIdx.x] = red_s[0];
}

// ---------------------------------------------------------------------------
__global__ void __launch_bounds__(256) final_reduce_kernel(float* __restrict__ out) {
    __shared__ double red[256];
    int tid = threadIdx.x;
    double s = 0.0;
    for (int i = tid; i < NPART; i += 256) s += (double)g_partials[i];
    red[tid] = s;
    __syncthreads();
    for (int off = 128; off; off >>= 1) {
        if (tid < off) red[tid] += red[tid + off];
        __syncthreads();
    }
    if (tid == 0) out[0] = (float)red[0];
}

// ---------------------------------------------------------------------------
extern "C" void kernel_launch(void* const* d_in, const int* in_sizes, int n_in,
                              void* d_out, int out_size) {
    const float* true_latent = (const float*)d_in[0];   // [B,T,F]
    const float* ctx         = (const float*)d_in[1];   // [B,T,C]
    const float* Wl          = (const float*)d_in[2];   // [F,C]
    const float* bl          = (const float*)d_in[3];   // [C]
    const float* Ws          = (const float*)d_in[4];   // [12]
    const float* bs          = (const float*)d_in[5];   // [12]
    const int*   neg         = (const int*)d_in[6];     // [B,NEG,T]
    float* out = (float*)d_out;

    cudaFuncSetAttribute(gemm_tl_tc, cudaFuncAttributeMaxDynamicSharedMemorySize,
                         (int)DYN_SM);

    convert_bf16<<<2048, 256>>>(true_latent, Wl);
    gemm_tl_tc<<<dim3(C_ / 128, (B_ * T_) / 128), 256, DYN_SM>>>(bl);
    loss_kernel<<<dim3(T_ / U_, B_), 256>>>(ctx, Ws, bs, neg);
    final_reduce_kernel<<<1, 256>>>(out);
}

// round 8
// speedup vs baseline: 1.9727x; 1.4289x over previous
#include <cuda_runtime.h>
#include <cuda_bf16.h>
#include <math.h>
#include <stdint.h>
#include <mma.h>

using namespace nvcuda;

#define B_      16
#define T_      2048
#define F_      512
#define C_      256
#define NEG_    10
#define COPIES  11
#define STEPS_  12
#define UB_     8                      // u per block in loss kernel
#define NPART   ((T_ / UB_) * B_)      // 4096

#define NA_ ((size_t)B_ * T_ * F_)
#define NW_ ((size_t)F_ * C_)

// Scratch (allocation-free rule: __device__ globals)
__device__ __nv_bfloat16  g_tl16[(size_t)B_ * T_ * C_];   // 16 MB projected latents (bf16)
__device__ float          g_tlsum[(size_t)B_ * T_];       // row sums of tl
__device__ __nv_bfloat16  g_A16[NA_];                     // 32 MB bf16 inputs
__device__ __nv_bfloat16  g_W16[NW_];
__device__ float          g_partials[NPART];

// ---------------------------------------------------------------------------
__device__ __forceinline__ uint32_t smem_u32(const void* p) {
    uint32_t a;
    asm("{ .reg .u64 t; cvta.to.shared.u64 t, %1; cvt.u32.u64 %0, t; }"
        : "=r"(a) : "l"(p));
    return a;
}
__device__ __forceinline__ void cp16(uint32_t dst, const void* src) {
    asm volatile("cp.async.cg.shared.global [%0], [%1], 16;"
                 :: "r"(dst), "l"(src) : "memory");
}
__device__ __forceinline__ void cp_commit() {
    asm volatile("cp.async.commit_group;" ::: "memory");
}
__device__ __forceinline__ void cp_wait1() {
    asm volatile("cp.async.wait_group 1;" ::: "memory");
}
__device__ __forceinline__ void cp_wait0() {
    asm volatile("cp.async.wait_group 0;" ::: "memory");
}

// ---------------------------------------------------------------------------
// Kernel 0: fp32 -> bf16 (RN) for A and W.
// ---------------------------------------------------------------------------
__global__ void __launch_bounds__(256) convert_bf16(
    const float* __restrict__ A, const float* __restrict__ W)
{
    const size_t nA4 = NA_ / 4, nW4 = NW_ / 4;
    const size_t stride = (size_t)gridDim.x * blockDim.x;
    for (size_t i = (size_t)blockIdx.x * blockDim.x + threadIdx.x;
         i < nA4 + nW4; i += stride) {
        union { __nv_bfloat162 h2[2]; uint2 u; } pk;
        if (i < nA4) {
            float4 v = ((const float4*)A)[i];
            pk.h2[0] = __float22bfloat162_rn(make_float2(v.x, v.y));
            pk.h2[1] = __float22bfloat162_rn(make_float2(v.z, v.w));
            ((uint2*)g_A16)[i] = pk.u;
        } else {
            size_t j = i - nA4;
            float4 v = ((const float4*)W)[j];
            pk.h2[0] = __float22bfloat162_rn(make_float2(v.x, v.y));
            pk.h2[1] = __float22bfloat162_rn(make_float2(v.z, v.w));
            ((uint2*)g_W16)[j] = pk.u;
        }
    }
}

// ---------------------------------------------------------------------------
// Kernel A: tl = A16 @ W16 + bl via BF16 wmma, fp32 acc, bf16 output.
// ---------------------------------------------------------------------------
#define GKC     32
#define SA_LD   40
#define SB_LD   136
#define SA_SZ   (128 * SA_LD)
#define SB_SZ   (GKC * SB_LD)
#define DYN_SM  (2 * (SA_SZ + SB_SZ) * sizeof(__nv_bfloat16))

__global__ void __launch_bounds__(256, 2) gemm_tl_tc(
    const float* __restrict__ bias)  // [C]
{
    extern __shared__ __nv_bfloat16 dynb[];
    __nv_bfloat16* sA = dynb;                 // [2][SA_SZ]
    __nv_bfloat16* sB = dynb + 2 * SA_SZ;     // [2][SB_SZ]
    __shared__ float epi[8][16 * 20];
    __shared__ float bias_s[128];

    const int tid  = threadIdx.x;
    const int bx   = blockIdx.x;
    const int by   = blockIdx.y;
    const int wid  = tid >> 5;
    const int lane = tid & 31;
    const int wm   = wid & 3;
    const int wn   = wid >> 2;

    if (tid < 128) bias_s[tid] = bias[bx * 128 + tid];

    wmma::fragment<wmma::accumulator, 16, 16, 16, float> acc[2][4];
#pragma unroll
    for (int i = 0; i < 2; i++)
#pragma unroll
        for (int j = 0; j < 4; j++) wmma::fill_fragment(acc[i][j], 0.f);

    const __nv_bfloat16* Abase = g_A16 + (size_t)(by * 128) * F_;
    const __nv_bfloat16* Wbase = g_W16 + bx * 128;

    const uint32_t sAu = smem_u32(sA);
    const uint32_t sBu = smem_u32(sB);

    uint32_t dA[2], dB[2];
    int arow[2], acol[2], brow[2], bcol[2];
#pragma unroll
    for (int q = 0; q < 2; q++) {
        int idx = tid + q * 256;
        arow[q] = idx >> 2;  acol[q] = (idx & 3) << 3;
        brow[q] = idx >> 4;  bcol[q] = (idx & 15) << 3;
        dA[q] = sAu + (uint32_t)(arow[q] * SA_LD + acol[q]) * 2u;
        dB[q] = sBu + (uint32_t)(brow[q] * SB_LD + bcol[q]) * 2u;
    }

    auto issue_tile = [&](int k0, int s) {
        uint32_t oA = (uint32_t)s * SA_SZ * 2u;
        uint32_t oB = (uint32_t)s * SB_SZ * 2u;
#pragma unroll
        for (int q = 0; q < 2; q++)
            cp16(dA[q] + oA, Abase + (size_t)arow[q] * F_ + k0 + acol[q]);
#pragma unroll
        for (int q = 0; q < 2; q++)
            cp16(dB[q] + oB, Wbase + (size_t)(k0 + brow[q]) * C_ + bcol[q]);
        cp_commit();
    };

    issue_tile(0, 0);

    const int NIT = F_ / GKC;
    for (int it = 0; it < NIT; ++it) {
        if (it + 1 < NIT) {
            issue_tile((it + 1) * GKC, (it + 1) & 1);
            cp_wait1();
        } else {
            cp_wait0();
        }
        __syncthreads();

        const __nv_bfloat16* cA = sA + (it & 1) * SA_SZ;
        const __nv_bfloat16* cB = sB + (it & 1) * SB_SZ;
#pragma unroll
        for (int ks = 0; ks < 2; ks++) {
            wmma::fragment<wmma::matrix_a, 16, 16, 16, __nv_bfloat16, wmma::row_major> af[2];
            wmma::fragment<wmma::matrix_b, 16, 16, 16, __nv_bfloat16, wmma::row_major> bf[4];
#pragma unroll
            for (int i = 0; i < 2; i++)
                wmma::load_matrix_sync(af[i], cA + (wm * 32 + i * 16) * SA_LD + ks * 16, SA_LD);
#pragma unroll
            for (int j = 0; j < 4; j++)
                wmma::load_matrix_sync(bf[j], cB + (ks * 16) * SB_LD + wn * 64 + j * 16, SB_LD);
#pragma unroll
            for (int i = 0; i < 2; i++)
#pragma unroll
                for (int j = 0; j < 4; j++)
                    wmma::mma_sync(acc[i][j], af[i], bf[j], acc[i][j]);
        }
        __syncthreads();
    }

    // Epilogue: smem bounce, add bias, convert to bf16, 16B store.
    const int row_l = lane >> 1;
    const int col_l = (lane & 1) * 8;
#pragma unroll
    for (int i = 0; i < 2; i++) {
#pragma unroll
        for (int j = 0; j < 4; j++) {
            wmma::store_matrix_sync(&epi[wid][0], acc[i][j], 20, wmma::mem_row_major);
            __syncwarp();
            int grow = by * 128 + wm * 32 + i * 16 + row_l;
            int bl0  = wn * 64 + j * 16 + col_l;
            int gcol = bx * 128 + bl0;
            const float* er = &epi[wid][row_l * 20 + col_l];
            union { __nv_bfloat162 h2[4]; uint4 u; } pk;
#pragma unroll
            for (int q = 0; q < 4; q++)
                pk.h2[q] = __float22bfloat162_rn(
                    make_float2(er[2 * q] + bias_s[bl0 + 2 * q],
                                er[2 * q + 1] + bias_s[bl0 + 2 * q + 1]));
            *(uint4*)&g_tl16[(size_t)grow * C_ + gcol] = pk.u;
            __syncwarp();
        }
    }
}

// ---------------------------------------------------------------------------
// Kernel S: tlsum[row] = sum_c tl16[row][c].  One warp per row.
// ---------------------------------------------------------------------------
__global__ void __launch_bounds__(256) tlsum_kernel() {
    const int row  = (blockIdx.x * blockDim.x + threadIdx.x) >> 5;
    const int lane = threadIdx.x & 31;
    union { uint4 u; __nv_bfloat162 h2[4]; } v;
    v.u = *(const uint4*)(g_tl16 + (size_t)row * C_ + lane * 8);
    float s = 0.f;
#pragma unroll
    for (int q = 0; q < 4; q++) {
        float2 f = __bfloat1622float2(v.h2[q]);
        s += f.x + f.y;
    }
#pragma unroll
    for (int o = 16; o; o >>= 1) s += __shfl_xor_sync(0xffffffffu, s, o);
    if (lane == 0) g_tlsum[row] = s;
}

// ---------------------------------------------------------------------------
// Kernel B: loss via per-warp 16x16x256 wmma.
// One warp per u. A = 16 ctx rows (window submatrix, rows u-11..u valid),
// B = 11 gathered target rows (+garbage pad). D[m][n] = dot(ctx[u-11+m], tgt_n),
// step i = 11-m. logit = Ws[i]*D + bs[i]*tlsum[tgt_n].
// ---------------------------------------------------------------------------
#define LDT      272                        // smem row ld in bf16 elems (544B)
#define CTXROWS  24                         // 19 valid + 5 pad
#define TGTROWS  (UB_ * COPIES + 5)         // 93
#define DYN_LOSS ((CTXROWS + TGTROWS) * LDT * sizeof(__nv_bfloat16))

__global__ void __launch_bounds__(256) loss_kernel(
    const float* __restrict__ ctx,   // [B, T, C]
    const float* __restrict__ Ws,    // [12]
    const float* __restrict__ bs,    // [12]
    const int*   __restrict__ neg)   // [B, NEG, T]
{
    extern __shared__ __nv_bfloat16 dynls[];
    __nv_bfloat16* ctx_s = dynls;                   // [CTXROWS][LDT]
    __nv_bfloat16* tgt_s = dynls + CTXROWS * LDT;   // [TGTROWS][LDT]
    __shared__ float epi[UB_][16 * 20];
    __shared__ float sums_s[UB_][16];
    __shared__ float ws_s[STEPS_], bs_s[STEPS_];
    __shared__ float red_s[256];

    const int b   = blockIdx.y;
    const int u0  = blockIdx.x * UB_;
    const int tid = threadIdx.x;

    if (tid < STEPS_) { ws_s[tid] = Ws[tid]; bs_s[tid] = bs[tid]; }

    // ctx window rows 0..18: row j = ctx[b, u0-11+j], fp32 -> bf16.
    for (int idx = tid; idx < 19 * (C_ / 4); idx += 256) {
        int j  = idx / (C_ / 4);
        int c4 = (idx % (C_ / 4)) * 4;
        int gr = u0 - 11 + j;
        float4 v = make_float4(0.f, 0.f, 0.f, 0.f);
        if (gr >= 0)
            v = *(const float4*)(ctx + ((size_t)b * T_ + gr) * C_ + c4);
        union { __nv_bfloat162 h2[2]; uint2 u; } pk;
        pk.h2[0] = __float22bfloat162_rn(make_float2(v.x, v.y));
        pk.h2[1] = __float22bfloat162_rn(make_float2(v.z, v.w));
        *(uint2*)(ctx_s + j * LDT + c4) = pk.u;
    }
    __syncthreads();

    const int warp = tid >> 5, lane = tid & 31;
    const int u = u0 + warp;

    // Gather 11 target rows (512B each = one LDG.128 per lane).
#pragma unroll
    for (int n = 0; n < COPIES; n++) {
        int r = (n == 0) ? u : neg[((size_t)b * NEG_ + (n - 1)) * T_ + u];
        uint4 v = *(const uint4*)(g_tl16 + ((size_t)b * T_ + r) * C_ + lane * 8);
        *(uint4*)(tgt_s + (warp * COPIES + n) * LDT + lane * 8) = v;
    }
    if (lane < COPIES) {
        int r = (lane == 0) ? u : neg[((size_t)b * NEG_ + (lane - 1)) * T_ + u];
        sums_s[warp][lane] = g_tlsum[(size_t)b * T_ + r];
    }
    __syncwarp();

    // 16x16x256 wmma chain.
    wmma::fragment<wmma::accumulator, 16, 16, 16, float> acc;
    wmma::fill_fragment(acc, 0.f);
    const __nv_bfloat16* Abase = ctx_s + warp * LDT;              // rows warp..warp+15
    const __nv_bfloat16* Bbase = tgt_s + (warp * COPIES) * LDT;
#pragma unroll
    for (int ks = 0; ks < C_ / 16; ks++) {
        wmma::fragment<wmma::matrix_a, 16, 16, 16, __nv_bfloat16, wmma::row_major> af;
        wmma::fragment<wmma::matrix_b, 16, 16, 16, __nv_bfloat16, wmma::col_major> bf;
        wmma::load_matrix_sync(af, Abase + ks * 16, LDT);
        wmma::load_matrix_sync(bf, Bbase + ks * 16, LDT);
        wmma::mma_sync(acc, af, bf, acc);
    }
    wmma::store_matrix_sync(&epi[warp][0], acc, 20, wmma::mem_row_major);
    __syncwarp();

    // LSE: lane m (0..11) handles step i = 11-m; valid when i <= u.
    float local = 0.f;
    if (lane < STEPS_) {
        const int m = lane, i = 11 - m;
        if (i <= u) {
            const float* row = &epi[warp][m * 20];
            const float w = ws_s[i], bb = bs_s[i];
            float lv[COPIES];
            float mx;
#pragma unroll
            for (int n = 0; n < COPIES; n++) {
                lv[n] = w * row[n] + bb * sums_s[warp][n];
                mx = (n == 0) ? lv[0] : fmaxf(mx, lv[n]);
            }
            float se = 0.f;
#pragma unroll
            for (int n = 0; n < COPIES; n++) se += expf(lv[n] - mx);
            local = mx + logf(se) - lv[0];
        }
    }

    red_s[tid] = local;
    __syncthreads();
    for (int off = 128; off; off >>= 1) {
        if (tid < off) red_s[tid] += red_s[tid + off];
        __syncthreads();
    }
    if (tid == 0)
        g_partials[blockIdx.y * (T_ / UB_) + blockIdx.x] = red_s[0];
}

// ---------------------------------------------------------------------------
__global__ void __launch_bounds__(256) final_reduce_kernel(float* __restrict__ out) {
    __shared__ double red[256];
    int tid = threadIdx.x;
    double s = 0.0;
    for (int i = tid; i < NPART; i += 256) s += (double)g_partials[i];
    red[tid] = s;
    __syncthreads();
    for (int off = 128; off; off >>= 1) {
        if (tid < off) red[tid] += red[tid + off];
        __syncthreads();
    }
    if (tid == 0) out[0] = (float)red[0];
}

// ---------------------------------------------------------------------------
extern "C" void kernel_launch(void* const* d_in, const int* in_sizes, int n_in,
                              void* d_out, int out_size) {
    const float* true_latent = (const float*)d_in[0];   // [B,T,F]
    const float* ctx         = (const float*)d_in[1];   // [B,T,C]
    const float* Wl          = (const float*)d_in[2];   // [F,C]
    const float* bl          = (const float*)d_in[3];   // [C]
    const float* Ws          = (const float*)d_in[4];   // [12]
    const float* bs          = (const float*)d_in[5];   // [12]
    const int*   neg         = (const int*)d_in[6];     // [B,NEG,T]
    float* out = (float*)d_out;

    cudaFuncSetAttribute(gemm_tl_tc, cudaFuncAttributeMaxDynamicSharedMemorySize,
                         (int)DYN_SM);
    cudaFuncSetAttribute(loss_kernel, cudaFuncAttributeMaxDynamicSharedMemorySize,
                         (int)DYN_LOSS);

    convert_bf16<<<2048, 256>>>(true_latent, Wl);
    gemm_tl_tc<<<dim3(C_ / 128, (B_ * T_) / 128), 256, DYN_SM>>>(bl);
    tlsum_kernel<<<(B_ * T_) / 8, 256>>>();
    loss_kernel<<<dim3(T_ / UB_, B_), 256, DYN_LOSS>>>(ctx, Ws, bs, neg);
    final_reduce_kernel<<<1, 256>>>(out);
}